// round 6
// baseline (speedup 1.0000x reference)
#include <cuda_runtime.h>
#include <cuda_fp16.h>
#include <cstdint>

#define NB 16
#define NC 512
#define NO 512
#define NH 64
#define NW 64

__device__ float g_wsq[NO * NC];
__device__ float g_siginv[NB * NO];
__device__ __half g_wh[9 * NO * NC];                   // [tap][o][i], c folded
__device__ __half g_xhh[(size_t)NB * 66 * 72 * 512];   // [b][row][px][ch], x*s, halo=0

// ---------------- prepass ----------------
__global__ void wsq_kernel(const float* __restrict__ w) {
    int idx = blockIdx.x * blockDim.x + threadIdx.x;
    if (idx >= NO * NC) return;
    const float* p = w + (size_t)idx * 9;
    float sum = 0.f;
#pragma unroll
    for (int t = 0; t < 9; t++) { float v = p[t]; sum += v * v; }
    g_wsq[idx] = sum;
}
__global__ void siginv_kernel(const float* __restrict__ s) {
    int gw = blockIdx.x * (blockDim.x >> 5) + (threadIdx.x >> 5);
    if (gw >= NB * NO) return;
    int b = gw >> 9, o = gw & 511, lane = threadIdx.x & 31;
    float sum = 0.f;
    for (int i = lane; i < NC; i += 32) {
        float sv = s[b * NC + i];
        sum += sv * sv * g_wsq[o * NC + i];
    }
#pragma unroll
    for (int off = 16; off > 0; off >>= 1)
        sum += __shfl_xor_sync(0xFFFFFFFFu, sum, off);
    if (lane == 0) g_siginv[gw] = rsqrtf(sum * (1.0f / (NC * 9)) + 1e-8f);
}
__global__ void wh_kernel(const float* __restrict__ w) {
    int idx = blockIdx.x * blockDim.x + threadIdx.x;
    if (idx >= 9 * NO * NC) return;
    int tap = idx >> 18, o = (idx >> 9) & 511, i = idx & 511;
    g_wh[idx] = __float2half(w[((size_t)o * NC + i) * 9 + tap] * rsqrtf((float)(NC * 9)));
}
__global__ void xhh_kernel(const float* __restrict__ x, const float* __restrict__ s) {
    const int r = blockIdx.x, b = blockIdx.y, tid = threadIdx.x;
    __half* dst = g_xhh + ((size_t)(b * 66 + r)) * 72 * 512;
    const int xrow = r - 1;
    if (xrow < 0 || xrow >= NH) {
        for (int e = tid; e < 72 * 512; e += 256) dst[e] = __float2half(0.f);
        return;
    }
    for (int e = tid; e < 8 * 512; e += 256) {      // zero px 0 and 65..71
        int pp = e >> 9, ch = e & 511;
        int p = (pp == 0) ? 0 : 64 + pp;
        dst[p * 512 + ch] = __float2half(0.f);
    }
    __shared__ float tile[32][65];
    for (int cb = 0; cb < 16; cb++) {
        __syncthreads();
        for (int e = tid; e < 32 * 64; e += 256) {
            int cc = e >> 6, px = e & 63;
            tile[cc][px] = x[(((size_t)b * 512 + cb * 32 + cc) * NH + xrow) * NW + px];
        }
        __syncthreads();
        for (int e = tid; e < 64 * 32; e += 256) {
            int px = e >> 5, cc = e & 31, ch = cb * 32 + cc;
            dst[(px + 1) * 512 + ch] = __float2half(tile[cc][px] * __ldg(&s[b * 512 + ch]));
        }
    }
}

// ---------------- main conv: fp16 mma + ldmatrix + cp.async, 512 thr ----------------
#define APITCH 24                       // halves per A row (48B, conflict-free ldmatrix)
#define BPITCH 24
#define ASZ (9 * 128 * APITCH)
#define BSZ (6 * 72 * BPITCH)
#define SMEM_BYTES ((2 * ASZ + 2 * BSZ) * 2)

#define CP16(dst, src) \
    asm volatile("cp.async.cg.shared.global [%0], [%1], 16;" :: "r"(dst), "l"(src))
#define CP_COMMIT() asm volatile("cp.async.commit_group;" ::: "memory")
#define LDMX4(r, a) asm volatile( \
    "ldmatrix.sync.aligned.m8n8.x4.shared.b16 {%0,%1,%2,%3}, [%4];" \
    : "=r"((r)[0]), "=r"((r)[1]), "=r"((r)[2]), "=r"((r)[3]) : "r"(a))
#define LDMX2(r0, r1, a) asm volatile( \
    "ldmatrix.sync.aligned.m8n8.x2.shared.b16 {%0,%1}, [%2];" \
    : "=r"(r0), "=r"(r1) : "r"(a))

__device__ __forceinline__ void mma_fp16(float d[4], const uint32_t a[4],
                                         uint32_t b0, uint32_t b1) {
    asm volatile(
        "mma.sync.aligned.m16n8k16.row.col.f32.f16.f16.f32 "
        "{%0,%1,%2,%3}, {%4,%5,%6,%7}, {%8,%9}, {%0,%1,%2,%3};\n"
        : "+f"(d[0]), "+f"(d[1]), "+f"(d[2]), "+f"(d[3])
        : "r"(a[0]), "r"(a[1]), "r"(a[2]), "r"(a[3]), "r"(b0), "r"(b1));
}

__global__ void __launch_bounds__(512, 1)
conv_fp16_kernel(float* __restrict__ out) {
    extern __shared__ __half sm[];
    const int b  = blockIdx.z;
    const int ob = blockIdx.y * 128;
    const int h0 = blockIdx.x * 4;

    const int tid  = threadIdx.x;
    const int lane = tid & 31;
    const int warp = tid >> 5;             // 0..15
    const int wm = warp >> 2;              // 0..3  -> 32-o slab
    const int wn = warp & 3;               // 0..3  -> image row
    const int g4 = lane >> 2;              // 0..7
    const int tg = lane & 3;

    uint32_t smbase;
    asm("{ .reg .u64 t; cvta.to.shared.u64 t, %1; cvt.u32.u64 %0, t; }"
        : "=r"(smbase) : "l"((const void*)sm));
    const uint32_t A0 = smbase;
    const uint32_t B0 = smbase + 2 * ASZ * 2;

    const int lg = lane >> 3, lr = lane & 7;
    // A: row = wm*32 + mt*16 + (lg&1)*8 + lr ; col = (lg>>1)*16B
    const uint32_t a_lane = (uint32_t)((wm * 32 + (lg & 1) * 8 + lr) * (APITCH * 2)
                                       + (lg >> 1) * 16);
    // B: row = (wn+dh)*72 + dw + nt*8 + lr ; col = (lg&1)*16B
    const uint32_t b_lane = (uint32_t)(lr * (BPITCH * 2) + (lg & 1) * 16);

    float acc[2][8][4];
#pragma unroll
    for (int mt = 0; mt < 2; mt++)
#pragma unroll
        for (int nt = 0; nt < 8; nt++)
#pragma unroll
            for (int q = 0; q < 4; q++) acc[mt][nt][q] = 0.f;

    const __half* wsrc = g_wh + ob * NC;
    const __half* xsrc = g_xhh + ((size_t)(b * 66 + h0)) * 72 * 512;

    auto load_chunk = [&](int c, int buf) {
        const uint32_t Ad = A0 + buf * ASZ * 2;
        const uint32_t Bd = B0 + buf * BSZ * 2;
#pragma unroll 2
        for (int e = tid; e < 2304; e += 512) {     // A: 9 tap * 128 o * 2 16B pieces
            int tap = e >> 8, rem = e & 255, o = rem >> 1, h = rem & 1;
            CP16(Ad + (uint32_t)((tap * 128 + o) * (APITCH * 2) + h * 16),
                 wsrc + ((size_t)tap * NO + o) * NC + c * 16 + h * 8);
        }
        for (int e = tid; e < 864; e += 512) {      // B: 6 rows * 72 px * 2 pieces
            int row = e / 144, rem = e - row * 144, px = rem >> 1, h = rem & 1;
            CP16(Bd + (uint32_t)((row * 72 + px) * (BPITCH * 2) + h * 16),
                 xsrc + ((size_t)(row * 72 + px)) * 512 + c * 16 + h * 8);
        }
        CP_COMMIT();
    };

    load_chunk(0, 0);

    for (int c = 0; c < 32; c++) {
        const int buf = c & 1;
        if (c + 1 < 32) {
            load_chunk(c + 1, buf ^ 1);
            asm volatile("cp.async.wait_group 1;" ::: "memory");
        } else {
            asm volatile("cp.async.wait_group 0;" ::: "memory");
        }
        __syncthreads();

        const uint32_t Abuf = A0 + buf * ASZ * 2;
        const uint32_t Bbuf = B0 + buf * BSZ * 2;
#pragma unroll
        for (int dh = 0; dh < 3; dh++) {
#pragma unroll
            for (int dw = 0; dw < 3; dw++) {
                const int tap = dh * 3 + dw;
                uint32_t a[2][4];
#pragma unroll
                for (int mt = 0; mt < 2; mt++)
                    LDMX4(a[mt], Abuf + (uint32_t)((tap * 128 + mt * 16) * (APITCH * 2))
                                 + a_lane);
                const uint32_t brow = Bbuf
                    + (uint32_t)(((wn + dh) * 72 + dw) * (BPITCH * 2)) + b_lane;
#pragma unroll
                for (int nt = 0; nt < 8; nt++) {
                    uint32_t b0, b1;
                    LDMX2(b0, b1, brow + (uint32_t)(nt * 8 * (BPITCH * 2)));
                    mma_fp16(acc[0][nt], a[0], b0, b1);
                    mma_fp16(acc[1][nt], a[1], b0, b1);
                }
            }
        }
        __syncthreads();
    }

    // epilogue
    const int h = h0 + wn;
#pragma unroll
    for (int mt = 0; mt < 2; mt++) {
        const int o0 = ob + wm * 32 + mt * 16 + g4;
        const float s0 = g_siginv[b * NO + o0];
        const float s1 = g_siginv[b * NO + o0 + 8];
#pragma unroll
        for (int nt = 0; nt < 8; nt++) {
            const int col = nt * 8 + tg * 2;
            float2 v0 = make_float2(acc[mt][nt][0] * s0, acc[mt][nt][1] * s0);
            float2 v1 = make_float2(acc[mt][nt][2] * s1, acc[mt][nt][3] * s1);
            *reinterpret_cast<float2*>(
                &out[(((size_t)b * NO + o0) * NH + h) * NW + col]) = v0;
            *reinterpret_cast<float2*>(
                &out[(((size_t)b * NO + o0 + 8) * NH + h) * NW + col]) = v1;
        }
    }
}

// ---------------------------------------------------------------------------
extern "C" void kernel_launch(void* const* d_in, const int* in_sizes, int n_in,
                              void* d_out, int out_size) {
    const float* x = (const float*)d_in[0];
    const float* s = (const float*)d_in[1];
    const float* w = (const float*)d_in[2];
    float* out = (float*)d_out;
    (void)in_sizes; (void)n_in; (void)out_size;

    wsq_kernel<<<(NO * NC + 255) / 256, 256>>>(w);
    siginv_kernel<<<(NB * NO) / 8, 256>>>(s);
    wh_kernel<<<(9 * NO * NC + 255) / 256, 256>>>(w);
    dim3 xg(66, NB);
    xhh_kernel<<<xg, 256>>>(x, s);

    cudaFuncSetAttribute(conv_fp16_kernel,
                         cudaFuncAttributeMaxDynamicSharedMemorySize, SMEM_BYTES);
    dim3 grid(16, NO / 128, NB);
    conv_fp16_kernel<<<grid, 512, SMEM_BYTES>>>(out);
}

// round 7
// speedup vs baseline: 1.0380x; 1.0380x over previous
#include <cuda_runtime.h>
#include <cuda_fp16.h>
#include <cstdint>

#define NB 16
#define NC 512
#define NO 512
#define NH 64
#define NW 64

__device__ float g_wsq[NO * NC];
__device__ float g_siginv[NB * NO];
__device__ __half g_wh[9 * NO * NC];                   // [tap][o][i], c folded
__device__ __half g_xhh[(size_t)NB * 66 * 72 * 512];   // [b][row][px][ch], x*s, halo=0

// ---------------- prepass ----------------
// fused: wsq + wh (one read of w)
__global__ void prep_w_kernel(const float* __restrict__ w) {
    int idx = blockIdx.x * blockDim.x + threadIdx.x;   // o*512 + i
    if (idx >= NO * NC) return;
    const float cc = rsqrtf((float)(NC * 9));
    const float* p = w + (size_t)idx * 9;
    float sum = 0.f;
#pragma unroll
    for (int t = 0; t < 9; t++) {
        float v = p[t];
        sum += v * v;
        g_wh[(t << 18) + idx] = __float2half(v * cc);
    }
    g_wsq[idx] = sum;
}
__global__ void siginv_kernel(const float* __restrict__ s) {
    int gw = blockIdx.x * (blockDim.x >> 5) + (threadIdx.x >> 5);
    if (gw >= NB * NO) return;
    int b = gw >> 9, o = gw & 511, lane = threadIdx.x & 31;
    float sum = 0.f;
    for (int i = lane; i < NC; i += 32) {
        float sv = s[b * NC + i];
        sum += sv * sv * g_wsq[o * NC + i];
    }
#pragma unroll
    for (int off = 16; off > 0; off >>= 1)
        sum += __shfl_xor_sync(0xFFFFFFFFu, sum, off);
    if (lane == 0) g_siginv[gw] = rsqrtf(sum * (1.0f / (NC * 9)) + 1e-8f);
}
__global__ void xhh_kernel(const float* __restrict__ x, const float* __restrict__ s) {
    const int r = blockIdx.x, b = blockIdx.y, tid = threadIdx.x;
    __half* dst = g_xhh + ((size_t)(b * 66 + r)) * 72 * 512;
    const int xrow = r - 1;
    if (xrow < 0 || xrow >= NH) {
        for (int e = tid; e < 72 * 512; e += 256) dst[e] = __float2half(0.f);
        return;
    }
    for (int e = tid; e < 8 * 512; e += 256) {      // zero px 0 and 65..71
        int pp = e >> 9, ch = e & 511;
        int p = (pp == 0) ? 0 : 64 + pp;
        dst[p * 512 + ch] = __float2half(0.f);
    }
    __shared__ float tile[32][65];
    for (int cb = 0; cb < 16; cb++) {
        __syncthreads();
        for (int e = tid; e < 32 * 64; e += 256) {
            int cc = e >> 6, px = e & 63;
            tile[cc][px] = x[(((size_t)b * 512 + cb * 32 + cc) * NH + xrow) * NW + px];
        }
        __syncthreads();
        for (int e = tid; e < 64 * 32; e += 256) {
            int px = e >> 5, cc = e & 31, ch = cb * 32 + cc;
            dst[(px + 1) * 512 + ch] = __float2half(tile[cc][px] * __ldg(&s[b * 512 + ch]));
        }
    }
}

// ---------------- main conv ----------------
#define APITCH 24                       // halves per A row (48B, conflict-free ldmatrix)
#define BPITCH 24
#define ASZ (9 * 128 * APITCH)          // halves per A stage
#define BSZ (6 * 72 * BPITCH)
#define NSTAGE 3
#define SMEM_BYTES (NSTAGE * (ASZ + BSZ) * 2)   // 196992

#define CP16(dst, src) \
    asm volatile("cp.async.cg.shared.global [%0], [%1], 16;" :: "r"(dst), "l"(src))
#define CP_COMMIT() asm volatile("cp.async.commit_group;" ::: "memory")
#define LDMX4(r, a) asm volatile( \
    "ldmatrix.sync.aligned.m8n8.x4.shared.b16 {%0,%1,%2,%3}, [%4];" \
    : "=r"((r)[0]), "=r"((r)[1]), "=r"((r)[2]), "=r"((r)[3]) : "r"(a))

__device__ __forceinline__ void mma_fp16(float d[4], const uint32_t a[4],
                                         uint32_t b0, uint32_t b1) {
    asm volatile(
        "mma.sync.aligned.m16n8k16.row.col.f32.f16.f16.f32 "
        "{%0,%1,%2,%3}, {%4,%5,%6,%7}, {%8,%9}, {%0,%1,%2,%3};\n"
        : "+f"(d[0]), "+f"(d[1]), "+f"(d[2]), "+f"(d[3])
        : "r"(a[0]), "r"(a[1]), "r"(a[2]), "r"(a[3]), "r"(b0), "r"(b1));
}

__global__ void __launch_bounds__(256, 1)
conv_fp16_kernel(float* __restrict__ out) {
    extern __shared__ __half sm[];
    const int b  = blockIdx.z;
    const int ob = blockIdx.y * 128;
    const int h0 = blockIdx.x * 4;

    const int tid  = threadIdx.x;
    const int lane = tid & 31;
    const int warp = tid >> 5;             // 0..7
    const int wm = warp >> 2;              // 0..1 -> 64-o slab
    const int wn = warp & 3;               // 0..3 -> image row
    const int g4 = lane >> 2;
    const int tg = lane & 3;

    uint32_t smbase;
    asm("{ .reg .u64 t; cvta.to.shared.u64 t, %1; cvt.u32.u64 %0, t; }"
        : "=r"(smbase) : "l"((const void*)sm));
    // stage layout: [stage][A then B]
    const uint32_t STG = (uint32_t)((ASZ + BSZ) * 2);

    const int lg = lane >> 3, lr = lane & 7;
    const uint32_t a_lane = (uint32_t)((wm * 64 + (lg & 1) * 8 + lr) * (APITCH * 2)
                                       + (lg >> 1) * 16);
    // B x4: lanes 0-7 px0-7 k-lo, 8-15 px0-7 k-hi, 16-23 px8-15 k-lo, 24-31 px8-15 k-hi
    const uint32_t b_lane = (uint32_t)((((lg >> 1) * 8) + lr) * (BPITCH * 2)
                                       + (lg & 1) * 16);

    float acc[4][8][4];
#pragma unroll
    for (int mt = 0; mt < 4; mt++)
#pragma unroll
        for (int nt = 0; nt < 8; nt++)
#pragma unroll
            for (int q = 0; q < 4; q++) acc[mt][nt][q] = 0.f;

    const __half* wsrc = g_wh + ob * NC;
    const __half* xsrc = g_xhh + ((size_t)(b * 66 + h0)) * 72 * 512;

    auto load_chunk = [&](int c, int stg) {
        const uint32_t Ad = smbase + stg * STG;
        const uint32_t Bd = Ad + ASZ * 2;
#pragma unroll 3
        for (int e = tid; e < 2304; e += 256) {     // A: 9 tap * 128 o * 2 16B pieces
            int tap = e >> 8, rem = e & 255, o = rem >> 1, h = rem & 1;
            CP16(Ad + (uint32_t)((tap * 128 + o) * (APITCH * 2) + h * 16),
                 wsrc + ((size_t)tap * NO + o) * NC + c * 16 + h * 8);
        }
#pragma unroll 2
        for (int e = tid; e < 864; e += 256) {      // B: 6 rows * 72 px * 2 pieces
            int row = e / 144, rem = e - row * 144, px = rem >> 1, h = rem & 1;
            CP16(Bd + (uint32_t)((row * 72 + px) * (BPITCH * 2) + h * 16),
                 xsrc + ((size_t)(row * 72 + px)) * 512 + c * 16 + h * 8);
        }
        CP_COMMIT();
    };

    load_chunk(0, 0);
    load_chunk(1, 1);

    for (int c = 0; c < 32; c++) {
        const int stg = c % NSTAGE;
        if (c + 2 < 32)
            asm volatile("cp.async.wait_group 1;" ::: "memory");
        else
            asm volatile("cp.async.wait_group 0;" ::: "memory");
        __syncthreads();
        if (c + 2 < 32) load_chunk(c + 2, (c + 2) % NSTAGE);

        const uint32_t Abuf = smbase + stg * STG;
        const uint32_t Bbuf = Abuf + ASZ * 2;
#pragma unroll
        for (int dh = 0; dh < 3; dh++) {
#pragma unroll
            for (int dw = 0; dw < 3; dw++) {
                const int tap = dh * 3 + dw;
                uint32_t a[4][4];
#pragma unroll
                for (int mt = 0; mt < 4; mt++)
                    LDMX4(a[mt], Abuf + (uint32_t)((tap * 128 + mt * 16) * (APITCH * 2))
                                 + a_lane);
                const uint32_t brow = Bbuf
                    + (uint32_t)(((wn + dh) * 72 + dw) * (BPITCH * 2)) + b_lane;
#pragma unroll
                for (int np = 0; np < 4; np++) {
                    uint32_t bb[4];
                    LDMX4(bb, brow + (uint32_t)(np * 16 * (BPITCH * 2)));
#pragma unroll
                    for (int mt = 0; mt < 4; mt++)
                        mma_fp16(acc[mt][2 * np], a[mt], bb[0], bb[1]);
#pragma unroll
                    for (int mt = 0; mt < 4; mt++)
                        mma_fp16(acc[mt][2 * np + 1], a[mt], bb[2], bb[3]);
                }
            }
        }
    }

    // epilogue
    const int h = h0 + wn;
#pragma unroll
    for (int mt = 0; mt < 4; mt++) {
        const int o0 = ob + wm * 64 + mt * 16 + g4;
        const float s0 = g_siginv[b * NO + o0];
        const float s1 = g_siginv[b * NO + o0 + 8];
#pragma unroll
        for (int nt = 0; nt < 8; nt++) {
            const int col = nt * 8 + tg * 2;
            float2 v0 = make_float2(acc[mt][nt][0] * s0, acc[mt][nt][1] * s0);
            float2 v1 = make_float2(acc[mt][nt][2] * s1, acc[mt][nt][3] * s1);
            *reinterpret_cast<float2*>(
                &out[(((size_t)b * NO + o0) * NH + h) * NW + col]) = v0;
            *reinterpret_cast<float2*>(
                &out[(((size_t)b * NO + o0 + 8) * NH + h) * NW + col]) = v1;
        }
    }
}

// ---------------------------------------------------------------------------
extern "C" void kernel_launch(void* const* d_in, const int* in_sizes, int n_in,
                              void* d_out, int out_size) {
    const float* x = (const float*)d_in[0];
    const float* s = (const float*)d_in[1];
    const float* w = (const float*)d_in[2];
    float* out = (float*)d_out;
    (void)in_sizes; (void)n_in; (void)out_size;

    prep_w_kernel<<<(NO * NC + 255) / 256, 256>>>(w);
    siginv_kernel<<<(NB * NO) / 8, 256>>>(s);
    dim3 xg(66, NB);
    xhh_kernel<<<xg, 256>>>(x, s);

    cudaFuncSetAttribute(conv_fp16_kernel,
                         cudaFuncAttributeMaxDynamicSharedMemorySize, SMEM_BYTES);
    dim3 grid(16, NO / 128, NB);
    conv_fp16_kernel<<<grid, 256, SMEM_BYTES>>>(out);
}